// round 11
// baseline (speedup 1.0000x reference)
#include <cuda_runtime.h>

#define Bz 4
#define Nz 8192
#define Mz 2048
#define Kz 20
#define Cz 64
#define PTS (Bz*Mz*Kz)   // 163840
#define NSLICE 8
#define SLEN 1024
#define NWORK 144
#define FUSED_SMEM (3*Nz*4)   // 96kB (FPS points; workers use 16kB of it as tile)

typedef unsigned long long ull;

// ---------------- packed f32x2 helpers (sm_100+: add/mul/fma only) ----------------
__device__ __forceinline__ ull PK(float lo, float hi) {
    ull r; asm("mov.b64 %0, {%1,%2};" : "=l"(r) : "f"(lo), "f"(hi)); return r;
}
__device__ __forceinline__ void UPK(ull v, float& lo, float& hi) {
    asm("mov.b64 {%0,%1}, %2;" : "=f"(lo), "=f"(hi) : "l"(v));
}
__device__ __forceinline__ ull ADD2(ull a, ull b) {
    ull r; asm("add.rn.f32x2 %0, %1, %2;" : "=l"(r) : "l"(a), "l"(b)); return r;
}
__device__ __forceinline__ ull MUL2(ull a, ull b) {
    ull r; asm("mul.rn.f32x2 %0, %1, %2;" : "=l"(r) : "l"(a), "l"(b)); return r;
}
__device__ __forceinline__ ull FMA2(ull a, ull b, ull c) {
    ull r; asm("fma.rn.f32x2 %0, %1, %2, %3;" : "=l"(r) : "l"(a), "l"(b), "l"(c)); return r;
}

// ---------------- scratch (static device globals; no allocation) ----------------
__device__ float4 g_q[Bz*Mz];                    // sampled pts: x,y,z,|q|^2
__device__ int    g_nidx[Bz*Mz*Kz];              // final knn indices
__device__ float  g_kd[Bz*Mz*NSLICE*Kz];         // per-slice partial top-20 dists
__device__ int    g_ki[Bz*Mz*NSLICE*Kz];         // per-slice partial top-20 idx
__device__ float  g_x1[(size_t)PTS*Cz];          // ~42MB
__device__ float  g_x2[(size_t)PTS*Cz];          // ~42MB
__device__ double g_sumA[2*Cz];                  // conv1-output stats
__device__ double g_sumB[2*Cz];                  // conv2-output stats
__device__ double g_sumC[2*Cz];                  // conv3-output stats
__device__ volatile unsigned g_prog[Bz];         // FPS progress per batch (handshake)

extern __shared__ float fused_sm[];

// ===== FPS role: 256 thr, 32 pts/thread, packed FMA dists, SINGLE barrier per step ===========
__device__ void fps_body(const float* __restrict__ p, int b) {
    const int tid = threadIdx.x;
    const float* pb = p + (size_t)b*Nz*3;
    float* spx = fused_sm; float* spy = fused_sm + Nz; float* spz = fused_sm + 2*Nz;
    __shared__ ull s_key[2][8];

    for (int i = tid; i < Nz; i += 256) {
        spx[i] = pb[3*i+0]; spy[i] = pb[3*i+1]; spz[i] = pb[3*i+2];
    }
    __syncthreads();

    ull px2[16], py2[16], pz2[16];
    float dd[32];
#pragma unroll
    for (int u = 0; u < 16; ++u) {
        int i0 = tid + (2*u)*256, i1 = i0 + 256;
        px2[u] = PK(spx[i0], spx[i1]);
        py2[u] = PK(spy[i0], spy[i1]);
        pz2[u] = PK(spz[i0], spz[i1]);
        dd[2*u] = 1e10f; dd[2*u+1] = 1e10f;
    }
    float lx = spx[0], ly = spy[0], lz = spz[0];
    if (tid == 0) {
        float qq = __fadd_rn(__fadd_rn(__fmul_rn(lx,lx), __fmul_rn(ly,ly)), __fmul_rn(lz,lz));
        g_q[b*Mz] = make_float4(lx, ly, lz, qq);
    }

    for (int t = 1; t < Mz; ++t) {
        const ull nx2 = PK(-lx,-lx), ny2 = PK(-ly,-ly), nz2 = PK(-lz,-lz);
        float m0[16];
#pragma unroll
        for (int u = 0; u < 16; ++u) {
            ull dx2 = ADD2(px2[u], nx2);
            ull dy2 = ADD2(py2[u], ny2);
            ull dz2 = ADD2(pz2[u], nz2);
            ull d2  = MUL2(dx2, dx2);
            d2 = FMA2(dy2, dy2, d2);
            d2 = FMA2(dz2, dz2, d2);
            float d0, d1; UPK(d2, d0, d1);
            float n0 = fminf(dd[2*u],   d0);
            float n1 = fminf(dd[2*u+1], d1);
            dd[2*u] = n0; dd[2*u+1] = n1;
            m0[u] = fmaxf(n0, n1);
        }
        // depth-4 max tree (preserves m0 for the candidate scan)
        float a8[8];
#pragma unroll
        for (int i = 0; i < 8; ++i) a8[i] = fmaxf(m0[i], m0[i+8]);
#pragma unroll
        for (int i = 0; i < 4; ++i) a8[i] = fmaxf(a8[i], a8[i+4]);
        a8[0] = fmaxf(a8[0], a8[2]); a8[1] = fmaxf(a8[1], a8[3]);
        const float bv = fmaxf(a8[0], a8[1]);
        // warp max (nonneg float bits monotone as u32)
        const unsigned wmax = __reduce_max_sync(0xffffffffu, __float_as_uint(bv));
        // warp-local lowest-index candidate (only max-holding threads scan)
        unsigned cand = 0xFFFFFFFFu;
        if (__float_as_uint(bv) == wmax) {
            const float bvg = __uint_as_float(wmax);
#pragma unroll
            for (int u = 15; u >= 0; --u)          // descending: last write = lowest index
                if (m0[u] == bvg)
                    cand = (dd[2*u] == bvg) ? (unsigned)(tid + (2*u)*256)
                                            : (unsigned)(tid + (2*u+1)*256);
        }
        const unsigned cmin = __reduce_min_sync(0xffffffffu, cand);
        const int buf = t & 1;
        if ((tid & 31) == 0)
            s_key[buf][tid >> 5] = (((ull)wmax) << 32) | (ull)(0xFFFFFFFFu - cmin);
        __syncthreads();                            // the ONLY barrier per step
        ull best = s_key[buf][0];
#pragma unroll
        for (int k = 1; k < 8; ++k) { ull v = s_key[buf][k]; if (v > best) best = v; }
        const unsigned wi = 0xFFFFFFFFu - (unsigned)(best & 0xFFFFFFFFull);
        lx = spx[wi]; ly = spy[wi]; lz = spz[wi];
        if (tid == 0) {
            float qq = __fadd_rn(__fadd_rn(__fmul_rn(lx,lx), __fmul_rn(ly,ly)), __fmul_rn(lz,lz));
            g_q[b*Mz + t] = make_float4(lx, ly, lz, qq);
            if ((t & 63) == 63) {                   // t=2047 publishes 2048
                __threadfence();
                g_prog[b] = (unsigned)(t + 1);
            }
        }
    }
}

// ===== kNN worker role: up to 2 units of (query-block qb, slice sl); spin on FPS progress ====
__device__ void knn_unit(const float* __restrict__ p, int e) {
    ull (*spt)[4] = (ull(*)[4])fused_sm;    // 16kB tile
    const int tid = threadIdx.x;
    const int qb = e & 31, sl = e >> 5;
    const int b  = qb >> 3;
    const float* pb = p + (size_t)b*Nz*3;
    const int t0 = sl * SLEN;

    for (int i = tid; i < SLEN/2; i += 256) {
        int i0 = t0 + 2*i, i1 = i0 + 1;
        float x0 = pb[3*i0+0], y0 = pb[3*i0+1], z0 = pb[3*i0+2];
        float x1 = pb[3*i1+0], y1 = pb[3*i1+1], z1 = pb[3*i1+2];
        float w0 = __fadd_rn(__fadd_rn(__fmul_rn(x0,x0), __fmul_rn(y0,y0)), __fmul_rn(z0,z0));
        float w1 = __fadd_rn(__fadd_rn(__fmul_rn(x1,x1), __fmul_rn(y1,y1)), __fmul_rn(z1,z1));
        spt[i][0] = PK(x0,x1); spt[i][1] = PK(y0,y1);
        spt[i][2] = PK(z0,z1); spt[i][3] = PK(w0,w1);
    }
    if (tid == 0) {                                   // producer guaranteed resident (one wave)
        const unsigned need = ((unsigned)(qb & 7) + 1u) * 256u;
        while (g_prog[b] < need) __nanosleep(256);
        __threadfence();
    }
    __syncthreads();

    const int qi = qb*256 + tid;
    const float4 q = g_q[qi];
    const ull qx2 = PK(q.x,q.x), qy2 = PK(q.y,q.y), qz2 = PK(q.z,q.z);
    const ull qw2 = PK(q.w,q.w), n2 = PK(-2.0f,-2.0f);

    float nd[Kz]; int ni[Kz];
#pragma unroll
    for (int j = 0; j < Kz; ++j) { nd[j] = 1e30f; ni[j] = 0; }
    float wk = 1e30f;

    for (int u = 0; u < SLEN/2; ++u) {
        const ulonglong2* r = (const ulonglong2*)spt[u];
        ulonglong2 r0 = r[0], r1 = r[1];
        ull a2 = MUL2(qx2, r0.x);
        a2 = FMA2(qy2, r0.y, a2);
        a2 = FMA2(qz2, r1.x, a2);
        ull a3 = ADD2(qw2, r1.y);
        ull d2 = FMA2(a2, n2, a3);
        float d0, d1; UPK(d2, d0, d1);
        if (d0 < wk) {
            float cd = d0; int ci = t0 + 2*u;
#pragma unroll
            for (int j = 0; j < Kz; ++j)
                if (cd < nd[j]) { float td = nd[j]; int ti = ni[j]; nd[j] = cd; ni[j] = ci; cd = td; ci = ti; }
            wk = nd[Kz-1];
        }
        if (d1 < wk) {
            float cd = d1; int ci = t0 + 2*u + 1;
#pragma unroll
            for (int j = 0; j < Kz; ++j)
                if (cd < nd[j]) { float td = nd[j]; int ti = ni[j]; nd[j] = cd; ni[j] = ci; cd = td; ci = ti; }
            wk = nd[Kz-1];
        }
    }
    const size_t base = ((size_t)qi*NSLICE + sl)*Kz;
#pragma unroll
    for (int j = 0; j < Kz; ++j) { g_kd[base+j] = nd[j]; g_ki[base+j] = ni[j]; }
}

// ===== fused kernel: 148 blocks = one wave, all resident -> spin cannot deadlock ==============
__global__ void __launch_bounds__(256,1) fused_kernel(const float* __restrict__ p) {
    if (blockIdx.x < Bz) {
        fps_body(p, blockIdx.x);
    } else {
        const int w = blockIdx.x - Bz;       // 0..143
        knn_unit(p, w);
        if (w + NWORK < 256) {
            __syncthreads();                 // protect smem tile reuse
            knn_unit(p, w + NWORK);
        }
    }
}

// ---- exact 8-way merge of per-slice sorted (d, idx) lists -> global top-20 ----
__global__ void __launch_bounds__(64) kmerge_kernel() {
    const int qi = blockIdx.x*64 + threadIdx.x;
    float dc[NSLICE]; int ic[NSLICE]; int h[NSLICE];
#pragma unroll
    for (int s = 0; s < NSLICE; ++s) {
        size_t base = ((size_t)qi*NSLICE + s)*Kz;
        dc[s] = g_kd[base]; ic[s] = g_ki[base]; h[s] = 0;
    }
    for (int j = 0; j < Kz; ++j) {
        int bs = 0;
#pragma unroll
        for (int s = 1; s < NSLICE; ++s)
            if (dc[s] < dc[bs] || (dc[s] == dc[bs] && ic[s] < ic[bs])) bs = s;
        g_nidx[(size_t)qi*Kz + j] = ic[bs];
        h[bs]++;
        if (h[bs] < Kz) {
            size_t off = ((size_t)qi*NSLICE + bs)*Kz + h[bs];
            dc[bs] = g_kd[off]; ic[bs] = g_ki[off];
        } else { dc[bs] = 3.0e38f; ic[bs] = 0x7FFFFFFF; }
    }
}

// ---- zero the stage accumulators (runs first; keeps replays deterministic) ----
__global__ void zero_kernel() {
    const int i = threadIdx.x;   // 128 threads
    g_sumA[i] = 0.0; g_sumB[i] = 0.0; g_sumC[i] = 0.0;
}

// ---- per-block BN affine from finalized sums (kernel boundary = sums complete) ----
__device__ __forceinline__ void compute_aff(const double* __restrict__ sum,
                                            const float* __restrict__ g,
                                            const float* __restrict__ bb,
                                            int c, float* sa, float* sc) {
    const double cnt = (double)PTS;
    double mean = sum[c] / cnt;
    double var  = sum[64 + c] / cnt - mean*mean;
    double inv  = 1.0 / sqrt(var + 1e-5);
    float a  = (float)((double)g[c] * inv);
    sa[c] = a;
    sc[c] = (float)((double)bb[c] - (double)a * mean);
}

// ====== conv1: 1 thread = 1 group-point, [6->64] matvec + leaky + fused BN stats ======
__global__ void __launch_bounds__(128) conv1_kernel(const float* __restrict__ p,
                                                    const float* __restrict__ W1) {
    __shared__ float sWc[64][8];
    __shared__ float so[128*68];
    __shared__ float sps[2][64], sqs[2][64];
    const int tid = threadIdx.x;
    if (tid < 64) {
#pragma unroll
        for (int j = 0; j < 6; ++j) sWc[tid][j] = W1[tid*6 + j];
        sWc[tid][6] = 0.f; sWc[tid][7] = 0.f;
    }
    const int gp0 = blockIdx.x * 128;
    const int gp = gp0 + tid;
    const int m = (gp / Kz) % Mz;
    const int b = gp / (Kz*Mz);
    const int nid = g_nidx[gp];
    const float* pr = p + ((size_t)b*Nz + nid)*3;
    float gx = pr[0], gy = pr[1], gz = pr[2];
    float4 q = g_q[b*Mz + m];
    float f0 = __fsub_rn(gx, q.x), f1 = __fsub_rn(gy, q.y), f2 = __fsub_rn(gz, q.z);
    __syncthreads();
#pragma unroll 4
    for (int c = 0; c < 64; ++c) {
        float4 w0 = *(const float4*)&sWc[c][0];
        float2 w1 = *(const float2*)&sWc[c][4];
        float acc = w0.x * f0;
        acc = fmaf(w0.y, f1, acc);
        acc = fmaf(w0.z, f2, acc);
        acc = fmaf(w0.w, gx, acc);
        acc = fmaf(w1.x, gy, acc);
        acc = fmaf(w1.y, gz, acc);
        so[tid*68 + c] = (acc >= 0.f) ? acc : 0.2f*acc;
    }
    __syncthreads();
    {
        int c = tid & 63, h = tid >> 6;
        float s = 0.f, s2 = 0.f;
#pragma unroll 8
        for (int r = h*64; r < h*64 + 64; ++r) {
            float v = so[r*68 + c];
            s += v; s2 = fmaf(v, v, s2);
        }
        sps[h][c] = s; sqs[h][c] = s2;
    }
    __syncthreads();
    if (tid < 64) {
        atomicAdd(&g_sumA[tid],      (double)(sps[0][tid] + sps[1][tid]));
        atomicAdd(&g_sumA[64 + tid], (double)(sqs[0][tid] + sqs[1][tid]));
    }
    for (int idx = tid; idx < 2048; idx += 128) {
        int row = idx >> 4, sg = idx & 15;
        float4 v = *(const float4*)&so[row*68 + sg*4];
        *(float4*)(g_x1 + (size_t)(gp0 + row)*64 + sg*4) = v;
    }
}

// ======== conv2/3: FFMA2 [64->64] matvec, inline BN affine, fused output stats ========
#define WJ 10
#define WCG (64*WJ + 4)
__global__ void __launch_bounds__(128) conv_kernel(int in_sel, const float* __restrict__ W,
                                                   const double* __restrict__ sumPrev,
                                                   const float* __restrict__ gPrev,
                                                   const float* __restrict__ bPrev,
                                                   double* __restrict__ sumOut) {
    const float* xin = in_sel ? g_x2 : g_x1;
    float*      xout = in_sel ? g_x1 : g_x2;
    __shared__ ull  sw[4*WCG];
    __shared__ float sx[128][65];
    __shared__ float sa[64], sc[64];
    __shared__ float ssumW[4*64], ssqW[4*64];
    const int tid = threadIdx.x;
    const int ww = tid >> 5, lane = tid & 31;

    if (tid < 64) compute_aff(sumPrev, gPrev, bPrev, tid, sa, sc);
    for (int k = tid; k < 2048; k += 128) {
        int cgk = k >> 9, rem = k & 511, j = rem >> 3, qq = rem & 7;
        int c0 = cgk*16 + 2*qq;
        sw[cgk*WCG + j*WJ + qq] = PK(W[c0*64 + j], W[(c0+1)*64 + j]);
    }
    __syncthreads();
    const int p0 = blockIdx.x * 128;
    for (int idx = tid; idx < 8192; idx += 128) {
        int j = idx & 63;
        float v = xin[(size_t)p0*64 + idx];
        sx[idx >> 6][j] = fmaf(sa[j], v, sc[j]);
    }
    __syncthreads();

    const int ptb = tid >> 2, cg = tid & 3;
    const ull* wbase = &sw[cg*WCG];
    ull acc[4][8];
#pragma unroll
    for (int k = 0; k < 4; ++k)
#pragma unroll
        for (int qq = 0; qq < 8; ++qq) acc[k][qq] = 0ull;

    for (int j = 0; j < 64; ++j) {
        const ulonglong2* wr = (const ulonglong2*)(wbase + j*WJ);
        ulonglong2 w01 = wr[0], w23 = wr[1], w45 = wr[2], w67 = wr[3];
        ull wv[8] = {w01.x, w01.y, w23.x, w23.y, w45.x, w45.y, w67.x, w67.y};
#pragma unroll
        for (int k = 0; k < 4; ++k) {
            float xv = sx[ptb + 32*k][j];
            ull xv2 = PK(xv, xv);
#pragma unroll
            for (int qq = 0; qq < 8; ++qq)
                acc[k][qq] = FMA2(wv[qq], xv2, acc[k][qq]);
        }
    }
    float sacc[16], sqacc[16];
#pragma unroll
    for (int i = 0; i < 16; ++i) { sacc[i] = 0.f; sqacc[i] = 0.f; }
#pragma unroll
    for (int k = 0; k < 4; ++k) {
        float o[16];
#pragma unroll
        for (int qq = 0; qq < 8; ++qq) {
            float lo, hi; UPK(acc[k][qq], lo, hi);
            o[2*qq]   = (lo >= 0.f) ? lo : 0.2f*lo;
            o[2*qq+1] = (hi >= 0.f) ? hi : 0.2f*hi;
        }
#pragma unroll
        for (int i = 0; i < 16; ++i) {
            sacc[i] += o[i];
            sqacc[i] = fmaf(o[i], o[i], sqacc[i]);
        }
        float4* op = (float4*)(xout + (size_t)(p0 + ptb + 32*k)*64 + cg*16);
#pragma unroll
        for (int v4 = 0; v4 < 4; ++v4)
            op[v4] = make_float4(o[4*v4], o[4*v4+1], o[4*v4+2], o[4*v4+3]);
    }
#pragma unroll
    for (int o = 4; o <= 16; o <<= 1) {
#pragma unroll
        for (int i = 0; i < 16; ++i) {
            sacc[i]  += __shfl_xor_sync(0xffffffffu, sacc[i],  o);
            sqacc[i] += __shfl_xor_sync(0xffffffffu, sqacc[i], o);
        }
    }
    if (lane < 4) {
#pragma unroll
        for (int i = 0; i < 16; ++i) {
            ssumW[ww*64 + lane*16 + i] = sacc[i];
            ssqW [ww*64 + lane*16 + i] = sqacc[i];
        }
    }
    __syncthreads();
    if (tid < 64) {
        float S = 0.f, Q = 0.f;
#pragma unroll
        for (int v = 0; v < 4; ++v) { S += ssumW[v*64 + tid]; Q += ssqW[v*64 + tid]; }
        atomicAdd(&sumOut[tid],      (double)S);
        atomicAdd(&sumOut[64 + tid], (double)Q);
    }
}

// ---------------- final: inline BN3 affine, max over K ----------------
__global__ void __launch_bounds__(256) maxk_kernel(float* __restrict__ out,
                                                   const float* __restrict__ g3,
                                                   const float* __restrict__ b3) {
    __shared__ float sa[64], sc[64];
    const int tid = threadIdx.x;
    if (tid < 64) compute_aff(g_sumC, g3, b3, tid, sa, sc);
    __syncthreads();
    const int t = blockIdx.x*256 + tid;
    const int c = t & 63;
    const int m = (t >> 6) & 2047;
    const int b = t >> 17;
    const float* base = g_x1 + ((size_t)(b*Mz + m)*Kz)*64 + c;
    const float a  = sa[c];
    const float cc = sc[c];
    float mx = -1e30f;
#pragma unroll
    for (int k = 0; k < Kz; ++k) {
        float v = fmaf(a, base[(size_t)k*64], cc);
        mx = fmaxf(mx, v);
    }
    out[((size_t)(b*64 + c))*Mz + m] = mx;
}

// ---------------- launch (single stream; fused FPS||kNN; 7 kernels) ----------------
extern "C" void kernel_launch(void* const* d_in, const int* in_sizes, int n_in,
                              void* d_out, int out_size) {
    (void)in_sizes; (void)n_in; (void)out_size;
    const float* p  = (const float*)d_in[0];
    const float* W1 = (const float*)d_in[1];
    const float* g1 = (const float*)d_in[2];
    const float* b1 = (const float*)d_in[3];
    const float* W2 = (const float*)d_in[4];
    const float* g2 = (const float*)d_in[5];
    const float* b2 = (const float*)d_in[6];
    const float* W3 = (const float*)d_in[7];
    const float* g3 = (const float*)d_in[8];
    const float* b3 = (const float*)d_in[9];
    float* out = (float*)d_out;

    double *sumA, *sumB, *sumC;
    cudaGetSymbolAddress((void**)&sumA, g_sumA);
    cudaGetSymbolAddress((void**)&sumB, g_sumB);
    cudaGetSymbolAddress((void**)&sumC, g_sumC);

    cudaFuncSetAttribute(fused_kernel, cudaFuncAttributeMaxDynamicSharedMemorySize, FUSED_SMEM);

    zero_kernel<<<1, 128>>>();
    fused_kernel<<<Bz + NWORK, 256, FUSED_SMEM>>>(p);
    kmerge_kernel<<<(Bz*Mz)/64, 64>>>();
    conv1_kernel<<<PTS/128, 128>>>(p, W1);
    conv_kernel<<<PTS/128, 128>>>(0, W2, sumA, g1, b1, sumB);
    conv_kernel<<<PTS/128, 128>>>(1, W3, sumB, g2, b2, sumC);
    maxk_kernel<<<(Bz*Mz*Cz)/256, 256>>>(out, g3, b3);
}